// round 13
// baseline (speedup 1.0000x reference)
#include <cuda_runtime.h>

#define NN 100000
#define NE 1600000
#define CH 64
#define NB_SCAN 98   // ceil(NN/1024)

// Device scratch (no allocs allowed)
__device__ int g_cnt[NN];                  // histogram, then write cursors
__device__ int g_off[NN];                  // exclusive offsets
__device__ int g_blksum[128];              // scan block sums
__device__ int g_srt[NE];                  // src ids sorted by dst
__device__ int g_idx_is64;

// ---------------------------------------------------------------------------
// Kernel 0: detect int64-vs-int32 edge_index (JAX x64-off narrows to int32).
// ---------------------------------------------------------------------------
__global__ void detect_k(const unsigned long long* __restrict__ ei) {
    if (threadIdx.x == 0 && blockIdx.x == 0) {
        int is64 = 1;
        for (int i = 0; i < 64; i++)
            if (ei[i] >= (unsigned long long)NN) { is64 = 0; break; }
        g_idx_is64 = is64;
    }
}

__device__ __forceinline__ int load_idx(const void* eiv, long long pos) {
    if (g_idx_is64) return (int)__ldg(&((const long long*)eiv)[pos]);
    return __ldg(&((const int*)eiv)[pos]);
}

// ---------------------------------------------------------------------------
// Sort pipeline: zero -> histogram -> block scan -> top scan -> add -> reorder
// ---------------------------------------------------------------------------
__global__ void zero_k() {
    int i = blockIdx.x * blockDim.x + threadIdx.x;
    if (i < NN) g_cnt[i] = 0;
}

__global__ void hist_k(const void* __restrict__ eiv) {
    int t = blockIdx.x * blockDim.x + threadIdx.x;
    if (t >= NE / 4) return;
    if (g_idx_is64) {
        #pragma unroll
        for (int q = 0; q < 4; q++)
            atomicAdd(&g_cnt[load_idx(eiv, (long long)NE + t * 4 + q)], 1);
    } else {
        const int4 d = __ldg((const int4*)eiv + NE / 4 + t);
        atomicAdd(&g_cnt[d.x], 1);
        atomicAdd(&g_cnt[d.y], 1);
        atomicAdd(&g_cnt[d.z], 1);
        atomicAdd(&g_cnt[d.w], 1);
    }
}

__global__ void __launch_bounds__(1024) scan_block_k() {
    __shared__ int warp_sums[32];
    const int tid = threadIdx.x;
    const int i = blockIdx.x * 1024 + tid;
    const int lane = tid & 31, warp = tid >> 5;
    int c = (i < NN) ? g_cnt[i] : 0;
    int v = c;
    #pragma unroll
    for (int d = 1; d < 32; d <<= 1) {
        int u = __shfl_up_sync(0xffffffffu, v, d);
        if (lane >= d) v += u;
    }
    if (lane == 31) warp_sums[warp] = v;
    __syncthreads();
    if (tid < 32) {
        int w = warp_sums[tid];
        #pragma unroll
        for (int d = 1; d < 32; d <<= 1) {
            int u = __shfl_up_sync(0xffffffffu, w, d);
            if (tid >= d) w += u;
        }
        warp_sums[tid] = w;  // inclusive per-warp totals
    }
    __syncthreads();
    const int wpref = warp ? warp_sums[warp - 1] : 0;
    if (i < NN) g_off[i] = wpref + v - c;      // exclusive within block
    if (tid == 1023) g_blksum[blockIdx.x] = wpref + v;
}

__global__ void scan_top_k() {   // 1 block, 128 threads over NB_SCAN sums
    __shared__ int ws[4];
    const int tid = threadIdx.x;
    const int lane = tid & 31, warp = tid >> 5;
    int c = (tid < NB_SCAN) ? g_blksum[tid] : 0;
    int v = c;
    #pragma unroll
    for (int d = 1; d < 32; d <<= 1) {
        int u = __shfl_up_sync(0xffffffffu, v, d);
        if (lane >= d) v += u;
    }
    if (lane == 31) ws[warp] = v;
    __syncthreads();
    if (tid == 0) {
        int s = 0;
        #pragma unroll
        for (int w = 0; w < 4; w++) { int t = ws[w]; ws[w] = s; s += t; }
    }
    __syncthreads();
    if (tid < NB_SCAN) g_blksum[tid] = ws[warp] + v - c;   // exclusive
}

__global__ void scan_add_k() {
    int i = blockIdx.x * blockDim.x + threadIdx.x;
    if (i < NN) {
        int o = g_off[i] + g_blksum[i >> 10];
        g_off[i] = o;
        g_cnt[i] = o;    // running cursor for reorder
    }
}

__global__ void reorder_k(const void* __restrict__ eiv) {
    int t = blockIdx.x * blockDim.x + threadIdx.x;
    if (t >= NE / 4) return;
    if (g_idx_is64) {
        #pragma unroll
        for (int q = 0; q < 4; q++) {
            int e = t * 4 + q;
            int src = load_idx(eiv, e);
            int dst = load_idx(eiv, (long long)NE + e);
            g_srt[atomicAdd(&g_cnt[dst], 1)] = src;
        }
    } else {
        const int4 s = __ldg((const int4*)eiv + t);
        const int4 d = __ldg((const int4*)eiv + NE / 4 + t);
        g_srt[atomicAdd(&g_cnt[d.x], 1)] = s.x;
        g_srt[atomicAdd(&g_cnt[d.y], 1)] = s.y;
        g_srt[atomicAdd(&g_cnt[d.z], 1)] = s.z;
        g_srt[atomicAdd(&g_cnt[d.w], 1)] = s.w;
    }
}

// ---------------------------------------------------------------------------
// Fused aggregation + MLP + gate. Tile = 128 nodes, 256 threads = 8 warps.
// Phase A: warp w aggregates rows 16w..16w+15 of the tile (warp-per-node
//          register accumulation over the sorted src list) into smem hs.
// Phase B: register-blocked MLP (RPT=8), channels 4t..4t+3, rows r+16n.
// No g_agg round-trip; phase-A L2 gather overlaps phase-B FMA across the
// 3 resident CTAs per SM.
// ---------------------------------------------------------------------------
#define NPT 128
#define RPT 8
#define TPB 256
#define HS_STRIDE 68
#define SMEM_FLOATS (2 * CH * CH + 2 * CH + NPT * HS_STRIDE)

__global__ void __launch_bounds__(TPB)
fused_k(const float2* __restrict__ x2,
        const float* __restrict__ W1, const float* __restrict__ b1,
        const float* __restrict__ W2, const float* __restrict__ b2,
        const float* __restrict__ alpha, float* __restrict__ out,
        int out_size) {
    extern __shared__ float smem[];
    float* sW1 = smem;                       // 4096
    float* sW2 = sW1 + CH * CH;              // 4096
    float* sb1 = sW2 + CH * CH;              // 64
    float* sb2 = sb1 + CH;                   // 64
    float* hs  = sb2 + CH;                   // 128 x 68

    const int tid = threadIdx.x;
    for (int i = tid; i < CH * CH; i += TPB) {
        sW1[i] = W1[i];
        sW2[i] = W2[i];
    }
    if (tid < CH) { sb1[tid] = b1[tid]; sb2[tid] = b2[tid]; }
    const float gate = 1.0f / (1.0f + expf(-alpha[0]));

    const int warp = tid >> 5, lane = tid & 31;
    const int t  = tid & 15;       // j-group (phase B)
    const int r  = tid >> 4;       // row lane (phase B)
    const int j4 = t * 4;
    __syncthreads();

    for (int base = blockIdx.x * NPT; base < NN; base += gridDim.x * NPT) {
        // ================= Phase A: aggregate 16 rows per warp =============
        #pragma unroll 1
        for (int i = 0; i < 16; i++) {
            const int row = warp * 16 + i;
            const int node = base + row;
            if (node < NN) {
                const int off0 = __ldg(&g_off[node]);
                const int off1 = (node + 1 < NN) ? __ldg(&g_off[node + 1]) : NE;

                float2 acc = x2[(size_t)node * 32 + lane];  // self (eps=0 GIN)
                int j = off0;
                for (; j + 4 <= off1; j += 4) {
                    int s0 = __ldg(&g_srt[j + 0]);
                    int s1 = __ldg(&g_srt[j + 1]);
                    int s2 = __ldg(&g_srt[j + 2]);
                    int s3 = __ldg(&g_srt[j + 3]);
                    float2 v0 = x2[(size_t)s0 * 32 + lane];
                    float2 v1 = x2[(size_t)s1 * 32 + lane];
                    float2 v2 = x2[(size_t)s2 * 32 + lane];
                    float2 v3 = x2[(size_t)s3 * 32 + lane];
                    acc.x += (v0.x + v1.x) + (v2.x + v3.x);
                    acc.y += (v0.y + v1.y) + (v2.y + v3.y);
                }
                for (; j < off1; j++) {
                    int s = __ldg(&g_srt[j]);
                    float2 v = x2[(size_t)s * 32 + lane];
                    acc.x += v.x; acc.y += v.y;
                }
                *reinterpret_cast<float2*>(&hs[row * HS_STRIDE + lane * 2]) = acc;
            }
        }
        __syncthreads();

        // ================= Phase B: MLP ====================================
        float4 acc[RPT];
        {
            const float4 bb = *reinterpret_cast<const float4*>(&sb1[j4]);
            #pragma unroll
            for (int n = 0; n < RPT; n++) acc[n] = bb;
        }
        #pragma unroll
        for (int k = 0; k < CH; k += 4) {
            const float4 w0 = *reinterpret_cast<const float4*>(&sW1[(k + 0) * CH + j4]);
            const float4 w1 = *reinterpret_cast<const float4*>(&sW1[(k + 1) * CH + j4]);
            const float4 w2 = *reinterpret_cast<const float4*>(&sW1[(k + 2) * CH + j4]);
            const float4 w3 = *reinterpret_cast<const float4*>(&sW1[(k + 3) * CH + j4]);
            #pragma unroll
            for (int n = 0; n < RPT; n++) {
                const float4 a = *reinterpret_cast<const float4*>(
                    &hs[(r + 16 * n) * HS_STRIDE + k]);
                acc[n].x += a.x * w0.x + a.y * w1.x + a.z * w2.x + a.w * w3.x;
                acc[n].y += a.x * w0.y + a.y * w1.y + a.z * w2.y + a.w * w3.y;
                acc[n].z += a.x * w0.z + a.y * w1.z + a.z * w2.z + a.w * w3.z;
                acc[n].w += a.x * w0.w + a.y * w1.w + a.z * w2.w + a.w * w3.w;
            }
        }
        __syncthreads();   // everyone done reading hs
        #pragma unroll
        for (int n = 0; n < RPT; n++) {
            float4 v = acc[n];
            v.x = fmaxf(v.x, 0.0f); v.y = fmaxf(v.y, 0.0f);
            v.z = fmaxf(v.z, 0.0f); v.w = fmaxf(v.w, 0.0f);
            *reinterpret_cast<float4*>(&hs[(r + 16 * n) * HS_STRIDE + j4]) = v;
        }
        __syncthreads();

        {
            const float4 bb = *reinterpret_cast<const float4*>(&sb2[j4]);
            #pragma unroll
            for (int n = 0; n < RPT; n++) acc[n] = bb;
        }
        #pragma unroll
        for (int k = 0; k < CH; k += 4) {
            const float4 w0 = *reinterpret_cast<const float4*>(&sW2[(k + 0) * CH + j4]);
            const float4 w1 = *reinterpret_cast<const float4*>(&sW2[(k + 1) * CH + j4]);
            const float4 w2 = *reinterpret_cast<const float4*>(&sW2[(k + 2) * CH + j4]);
            const float4 w3 = *reinterpret_cast<const float4*>(&sW2[(k + 3) * CH + j4]);
            #pragma unroll
            for (int n = 0; n < RPT; n++) {
                const float4 a = *reinterpret_cast<const float4*>(
                    &hs[(r + 16 * n) * HS_STRIDE + k]);
                acc[n].x += a.x * w0.x + a.y * w1.x + a.z * w2.x + a.w * w3.x;
                acc[n].y += a.x * w0.y + a.y * w1.y + a.z * w2.y + a.w * w3.y;
                acc[n].z += a.x * w0.z + a.y * w1.z + a.z * w2.z + a.w * w3.z;
                acc[n].w += a.x * w0.w + a.y * w1.w + a.z * w2.w + a.w * w3.w;
            }
        }
        #pragma unroll
        for (int n = 0; n < RPT; n++) {
            const int node = base + r + 16 * n;
            if (node < NN) {
                float4 o = make_float4(gate * acc[n].x, gate * acc[n].y,
                                       gate * acc[n].z, gate * acc[n].w);
                *reinterpret_cast<float4*>(out + (size_t)node * CH + j4) = o;
            }
        }
        __syncthreads();   // protect hs before next tile
    }

    // Tail: reference also returns gate (flattened after main output).
    const int extra = out_size - NN * CH;
    if (blockIdx.x == 0 && tid < extra) out[NN * CH + tid] = gate;
}

// ---------------------------------------------------------------------------
extern "C" void kernel_launch(void* const* d_in, const int* in_sizes, int n_in,
                              void* d_out, int out_size) {
    const float* x     = (const float*)d_in[0];
    const void*  ei    = d_in[1];
    const float* W1    = (const float*)d_in[2];
    const float* b1    = (const float*)d_in[3];
    const float* W2    = (const float*)d_in[4];
    const float* b2    = (const float*)d_in[5];
    const float* alpha = (const float*)d_in[6];
    float*       out   = (float*)d_out;

    detect_k<<<1, 32>>>((const unsigned long long*)ei);

    zero_k<<<(NN + 255) / 256, 256>>>();
    hist_k<<<(NE / 4 + 255) / 256, 256>>>(ei);
    scan_block_k<<<NB_SCAN, 1024>>>();
    scan_top_k<<<1, 128>>>();
    scan_add_k<<<(NN + 255) / 256, 256>>>();
    reorder_k<<<(NE / 4 + 255) / 256, 256>>>(ei);

    static const size_t smem_bytes = SMEM_FLOATS * sizeof(float);
    cudaFuncSetAttribute(fused_k, cudaFuncAttributeMaxDynamicSharedMemorySize,
                         (int)smem_bytes);
    fused_k<<<444, TPB, smem_bytes>>>(
        reinterpret_cast<const float2*>(x),
        W1, b1, W2, b2, alpha, out, out_size);
}